// round 4
// baseline (speedup 1.0000x reference)
#include <cuda_runtime.h>
#include <cstdint>

// ============================================================================
// BitNet b1.58 FFN  — int8 tensor-core (mma.sync IMMA) implementation
//
// tokens T = 8*8192 = 65536, D = 512, F = 2048
// Pipeline:
//   1. w_scale = max(mean|w|, EPS)   (deterministic 2-pass reduction, both w)
//   2. ternary-quantize weights to int8 {-1,0,1}
//   3. per-token int8 quantize x, record fac1 = s_w1 * max|x| / 127
//   4. GEMM1 (int8) -> relu -> rint -> clamp 127 -> int8 h2 scratch
//   5. per-token max over h2, re-quantize in place, fac2 = s_w2 * max / 127
//   6. GEMM2 (int8) -> fp32 out = intdot * fac2[token]
// All integer dots are exact; only quant-boundary ULP flips differ from ref.
// ============================================================================

#define T_TOK 65536
#define D_IN  512
#define F_FF  2048
#define EPSF  1e-5f

static __device__ float       g_part[256];
static __device__ float       g_ws[2];
static __device__ signed char g_wupq[(size_t)F_FF * D_IN];
static __device__ signed char g_wdq [(size_t)D_IN * F_FF];
static __device__ signed char g_xq  [(size_t)T_TOK * D_IN];
static __device__ float       g_fac1[T_TOK];
static __device__ signed char g_h2  [(size_t)T_TOK * F_FF];   // 128 MB scratch
static __device__ float       g_fac2[T_TOK];

// ---------------------------------------------------------------------------
// deterministic |w| sum reduction (fixed grid, fixed order)
// ---------------------------------------------------------------------------
__global__ void k_abs_partial(const float* __restrict__ w, int n) {
    __shared__ float s[256];
    int tid = threadIdx.x;
    float acc = 0.f;
    for (int i = blockIdx.x * 256 + tid; i < n; i += 256 * 256)
        acc += fabsf(w[i]);
    s[tid] = acc;
    __syncthreads();
    for (int o = 128; o; o >>= 1) {
        if (tid < o) s[tid] += s[tid + o];
        __syncthreads();
    }
    if (tid == 0) g_part[blockIdx.x] = s[0];
}

__global__ void k_ws_final(int n, int idx) {
    __shared__ float s[256];
    int tid = threadIdx.x;
    s[tid] = g_part[tid];
    __syncthreads();
    for (int o = 128; o; o >>= 1) {
        if (tid < o) s[tid] += s[tid + o];
        __syncthreads();
    }
    if (tid == 0) g_ws[idx] = fmaxf(s[0] / (float)n, EPSF);
}

// ---------------------------------------------------------------------------
// ternary weight quantization:  q = clip(rint(w/s), -1, 1)
// ---------------------------------------------------------------------------
__global__ void k_quant_w(const float* __restrict__ w, signed char* __restrict__ q,
                          int n, int idx) {
    int i = blockIdx.x * blockDim.x + threadIdx.x;
    if (i < n) {
        float s = g_ws[idx];
        float r = rintf(w[i] / s);
        r = fminf(fmaxf(r, -1.f), 1.f);
        q[i] = (signed char)(int)r;
    }
}

// ---------------------------------------------------------------------------
// per-token int8 quantization of x; one block (128 thr) per token
// ---------------------------------------------------------------------------
__global__ void k_quant_x(const float* __restrict__ x) {
    int t = blockIdx.x, tid = threadIdx.x;
    const float4* xr = (const float4*)(x + (size_t)t * D_IN);
    float4 v = xr[tid];
    float m = fmaxf(fmaxf(fabsf(v.x), fabsf(v.y)), fmaxf(fabsf(v.z), fabsf(v.w)));
#pragma unroll
    for (int o = 16; o; o >>= 1) m = fmaxf(m, __shfl_xor_sync(~0u, m, o));
    __shared__ float sm[4];
    if ((tid & 31) == 0) sm[tid >> 5] = m;
    __syncthreads();
    float maxc = fmaxf(fmaxf(fmaxf(sm[0], sm[1]), fmaxf(sm[2], sm[3])), EPSF);
    float scale = 127.f / maxc;
    auto q = [&](float f) -> int {
        float r = rintf(f * scale);
        r = fminf(fmaxf(r, -128.f), 127.f);
        return (int)r;
    };
    int q0 = q(v.x) & 0xff, q1 = q(v.y) & 0xff, q2 = q(v.z) & 0xff, q3 = q(v.w) & 0xff;
    unsigned packed = q0 | (q1 << 8) | (q2 << 16) | (q3 << 24);
    ((unsigned*)g_xq)[(size_t)t * (D_IN / 4) + tid] = packed;
    if (tid == 0) g_fac1[t] = g_ws[0] * maxc * (1.f / 127.f);
}

// ---------------------------------------------------------------------------
// per-token re-quantization of h2 (in place); one block (256 thr) per token
// ---------------------------------------------------------------------------
__global__ void k_quant_h() {
    int t = blockIdx.x, tid = threadIdx.x;
    size_t base = (size_t)t * F_FF;
    int2 d = ((const int2*)(g_h2 + base))[tid];
    signed char b[8];
    *(int2*)b = d;
    int m = 0;
#pragma unroll
    for (int i = 0; i < 8; i++) m = max(m, (int)b[i]);
#pragma unroll
    for (int o = 16; o; o >>= 1) m = max(m, __shfl_xor_sync(~0u, m, o));
    __shared__ int sm[8];
    if ((tid & 31) == 0) sm[tid >> 5] = m;
    __syncthreads();
    int M = 0;
#pragma unroll
    for (int i = 0; i < 8; i++) M = max(M, sm[i]);
    float maxc = fmaxf((float)M, EPSF);
    float scale = 127.f / maxc;
#pragma unroll
    for (int i = 0; i < 8; i++) {
        float r = rintf((float)b[i] * scale);
        r = fminf(r, 127.f);
        b[i] = (signed char)(int)r;
    }
    ((int2*)(g_h2 + base))[tid] = *(int2*)b;
    if (tid == 0) g_fac2[t] = g_ws[1] * maxc * (1.f / 127.f);
}

// ---------------------------------------------------------------------------
// int8 GEMM: C[M,N] = A[M,K] (row-major) * B[N,K]^T (B row-major [N,K])
// 128x128 block tile, K-chunk 64, cp.async double-buffered, mma.m16n8k32.s8
// MODE 1: relu+rint+clamp127 -> int8 to oq ; MODE 2: *fac -> fp32 to of
// ---------------------------------------------------------------------------
__device__ __forceinline__ void cp16(void* s, const void* g) {
    unsigned sa = (unsigned)__cvta_generic_to_shared(s);
    asm volatile("cp.async.cg.shared.global [%0], [%1], 16;\n" :: "r"(sa), "l"(g));
}

__device__ __forceinline__ void mma8(int* c, const int* a, const int* b) {
    asm volatile(
        "mma.sync.aligned.m16n8k32.row.col.s32.s8.s8.s32 "
        "{%0,%1,%2,%3}, {%4,%5,%6,%7}, {%8,%9}, {%0,%1,%2,%3};\n"
        : "+r"(c[0]), "+r"(c[1]), "+r"(c[2]), "+r"(c[3])
        : "r"(a[0]), "r"(a[1]), "r"(a[2]), "r"(a[3]), "r"(b[0]), "r"(b[1]));
}

template <int MODE>
__global__ void __launch_bounds__(256, 2)
gemm_s8(const signed char* __restrict__ A, const signed char* __restrict__ B,
        int K, int N, const float* __restrict__ fac,
        signed char* __restrict__ oq, float* __restrict__ of) {
    constexpr int RB = 80;  // 64B K-chunk + 16B pad (bank-conflict-free frag loads)
    __shared__ signed char sA[2][128 * RB];
    __shared__ signed char sB[2][128 * RB];
    const int tid  = threadIdx.x;
    const int warp = tid >> 5, lane = tid & 31;
    const int wm = warp >> 2, wn = warp & 3;   // 2x4 warp grid; warp tile 64x32
    const int gq = lane >> 2, qid = lane & 3;
    const int bm = blockIdx.y, bn = blockIdx.x;

    const signed char* Ab = A + (size_t)bm * 128 * K;
    const signed char* Bb = B + (size_t)bn * 128 * K;

    int c[4][4][4];
#pragma unroll
    for (int i = 0; i < 4; i++)
#pragma unroll
        for (int j = 0; j < 4; j++)
#pragma unroll
            for (int k = 0; k < 4; k++) c[i][j][k] = 0;

    const int KT = K >> 6;

    auto load_stage = [&](int s, int kt) {
        const int k0 = kt << 6;
#pragma unroll
        for (int i = 0; i < 2; i++) {
            int idx = tid + (i << 8);
            int row = idx >> 2, cc = (idx & 3) << 4;
            cp16(&sA[s][row * RB + cc], Ab + (size_t)row * K + k0 + cc);
            cp16(&sB[s][row * RB + cc], Bb + (size_t)row * K + k0 + cc);
        }
        asm volatile("cp.async.commit_group;\n");
    };

    load_stage(0, 0);

    for (int kt = 0; kt < KT; ++kt) {
        const int s = kt & 1;
        if (kt + 1 < KT) {
            load_stage(s ^ 1, kt + 1);
            asm volatile("cp.async.wait_group 1;\n");
        } else {
            asm volatile("cp.async.wait_group 0;\n");
        }
        __syncthreads();
#pragma unroll
        for (int ks = 0; ks < 2; ++ks) {
            const int koff = (ks << 5) + (qid << 2);
            int a[4][4], b[4][2];
#pragma unroll
            for (int mt = 0; mt < 4; ++mt) {
                const signed char* p = &sA[s][(wm * 64 + mt * 16 + gq) * RB + koff];
                a[mt][0] = *(const int*)p;
                a[mt][1] = *(const int*)(p + 8 * RB);
                a[mt][2] = *(const int*)(p + 16);
                a[mt][3] = *(const int*)(p + 8 * RB + 16);
            }
#pragma unroll
            for (int nt = 0; nt < 4; ++nt) {
                const signed char* p = &sB[s][(wn * 32 + nt * 8 + gq) * RB + koff];
                b[nt][0] = *(const int*)p;
                b[nt][1] = *(const int*)(p + 16);
            }
#pragma unroll
            for (int mt = 0; mt < 4; ++mt)
#pragma unroll
                for (int nt = 0; nt < 4; ++nt) mma8(c[mt][nt], a[mt], b[nt]);
        }
        __syncthreads();
    }

    // epilogue
    const int rbase = bm * 128 + wm * 64;
    const int cbase = bn * 128 + wn * 32;
#pragma unroll
    for (int mt = 0; mt < 4; ++mt) {
        int r0 = rbase + mt * 16 + gq;
        float f0 = fac[r0], f1 = fac[r0 + 8];
#pragma unroll
        for (int nt = 0; nt < 4; ++nt) {
            int col = cbase + nt * 8 + qid * 2;
            if (MODE == 1) {
                auto qz = [](int v, float f) -> unsigned {
                    float h = (float)v * f;
                    h = fmaxf(h, 0.f);          // relu
                    float r = rintf(h);          // round (half-even, matches jnp)
                    r = fminf(r, 127.f);         // clamp
                    return (unsigned)(int)r;
                };
                unsigned p0 = qz(c[mt][nt][0], f0) | (qz(c[mt][nt][1], f0) << 8);
                *(unsigned short*)(oq + (size_t)r0 * N + col) = (unsigned short)p0;
                unsigned p1 = qz(c[mt][nt][2], f1) | (qz(c[mt][nt][3], f1) << 8);
                *(unsigned short*)(oq + (size_t)(r0 + 8) * N + col) = (unsigned short)p1;
            } else {
                float2 v0 = make_float2((float)c[mt][nt][0] * f0, (float)c[mt][nt][1] * f0);
                *(float2*)(of + (size_t)r0 * N + col) = v0;
                float2 v1 = make_float2((float)c[mt][nt][2] * f1, (float)c[mt][nt][3] * f1);
                *(float2*)(of + (size_t)(r0 + 8) * N + col) = v1;
            }
        }
    }
}

// ---------------------------------------------------------------------------
extern "C" void kernel_launch(void* const* d_in, const int* in_sizes, int n_in,
                              void* d_out, int out_size) {
    const float* x      = (const float*)d_in[0];   // [8,8192,512]
    const float* w_up   = (const float*)d_in[1];   // [2048,512]
    const float* w_down = (const float*)d_in[2];   // [512,2048]
    float* out = (float*)d_out;                    // [8,8192,512]

    void *p_wupq = 0, *p_wdq = 0, *p_xq = 0, *p_fac1 = 0, *p_h2 = 0, *p_fac2 = 0;
    cudaGetSymbolAddress(&p_wupq, g_wupq);
    cudaGetSymbolAddress(&p_wdq,  g_wdq);
    cudaGetSymbolAddress(&p_xq,   g_xq);
    cudaGetSymbolAddress(&p_fac1, g_fac1);
    cudaGetSymbolAddress(&p_h2,   g_h2);
    cudaGetSymbolAddress(&p_fac2, g_fac2);

    const int NW = F_FF * D_IN;  // 1048576 (both weight matrices)

    // weight scales (deterministic)
    k_abs_partial<<<256, 256>>>(w_up, NW);
    k_ws_final<<<1, 256>>>(NW, 0);
    k_abs_partial<<<256, 256>>>(w_down, NW);
    k_ws_final<<<1, 256>>>(NW, 1);

    // ternary weights
    k_quant_w<<<(NW + 255) / 256, 256>>>(w_up,   (signed char*)p_wupq, NW, 0);
    k_quant_w<<<(NW + 255) / 256, 256>>>(w_down, (signed char*)p_wdq,  NW, 1);

    // per-token x quantization
    k_quant_x<<<T_TOK, 128>>>(x);

    // GEMM1: [T,512] x [2048,512]^T -> int8 h2
    gemm_s8<1><<<dim3(F_FF / 128, T_TOK / 128), 256>>>(
        (const signed char*)p_xq, (const signed char*)p_wupq,
        D_IN, F_FF, (const float*)p_fac1, (signed char*)p_h2, nullptr);

    // re-quantize h2 per token
    k_quant_h<<<T_TOK, 256>>>();

    // GEMM2: [T,2048] x [512,2048]^T -> fp32 out
    gemm_s8<2><<<dim3(D_IN / 128, T_TOK / 128), 256>>>(
        (const signed char*)p_h2, (const signed char*)p_wdq,
        F_FF, D_IN, (const float*)p_fac2, nullptr, out);
}